// round 4
// baseline (speedup 1.0000x reference)
#include <cuda_runtime.h>
#include <cstdint>

#define T_DIM     1024
#define SEQ_LEN   8192
#define STATE_LEN 4096

// Scratch (no cudaMalloc allowed): histogram of his as float, normalized table.
__device__ float g_hist[T_DIM];
__device__ float g_ntbl[T_DIM * T_DIM];   // 4 MB: ntbl[t][t'] = exp(mat[t,t']-max_t)/denom_t

// ---------------- K1: histogram of his (1 block, 1024 threads) ----------------
__global__ __launch_bounds__(1024)
void hist_kernel(const int* __restrict__ his)
{
    __shared__ int sh[T_DIM];
    const int tid = threadIdx.x;
    sh[tid] = 0;
    __syncthreads();
    #pragma unroll
    for (int k = 0; k < SEQ_LEN / 1024; k++)
        atomicAdd(&sh[his[tid + k * 1024]], 1);
    __syncthreads();
    g_hist[tid] = (float)sh[tid];
}

// ---------------- K2: normalized softmax tables (1024 blocks, 256 thr) ----------------
__global__ __launch_bounds__(256)
void table_kernel(const float* __restrict__ mat)
{
    __shared__ float redm[8];
    __shared__ float reds[8];

    const int t    = blockIdx.x;
    const int tid  = threadIdx.x;
    const int lane = tid & 31;
    const int wid  = tid >> 5;

    float4 rv = reinterpret_cast<const float4*>(mat + (size_t)t * T_DIM)[tid];

    // block max
    float m = fmaxf(fmaxf(rv.x, rv.y), fmaxf(rv.z, rv.w));
    #pragma unroll
    for (int o = 16; o; o >>= 1)
        m = fmaxf(m, __shfl_xor_sync(0xffffffffu, m, o));
    if (lane == 0) redm[wid] = m;
    __syncthreads();
    float bm = redm[0];
    #pragma unroll
    for (int w = 1; w < 8; w++) bm = fmaxf(bm, redm[w]);

    // exp + histogram-weighted denominator
    float4 e;
    e.x = __expf(rv.x - bm);
    e.y = __expf(rv.y - bm);
    e.z = __expf(rv.z - bm);
    e.w = __expf(rv.w - bm);

    float4 h = reinterpret_cast<const float4*>(g_hist)[tid];
    float s = h.x * e.x + h.y * e.y + h.z * e.z + h.w * e.w;
    #pragma unroll
    for (int o = 16; o; o >>= 1)
        s += __shfl_xor_sync(0xffffffffu, s, o);
    if (lane == 0) reds[wid] = s;
    __syncthreads();
    float tot = 0.0f;
    #pragma unroll
    for (int w = 0; w < 8; w++) tot += reds[w];
    const float inv = 1.0f / tot;

    float4 o4;
    o4.x = e.x * inv;
    o4.y = e.y * inv;
    o4.z = e.z * inv;
    o4.w = e.w * inv;
    reinterpret_cast<float4*>(g_ntbl)[(size_t)t * (T_DIM / 4) + tid] = o4;
}

// ---------------- K3: gather + coalesced write (512 blocks, 256 thr) ----------------
#define THREADS        256
#define ROWS_PER_BLOCK 8
#define VEC_ITERS      (SEQ_LEN / 4 / THREADS)   // 8

__global__ __launch_bounds__(THREADS)
void gather_kernel(const int* __restrict__ his,
                   const int* __restrict__ cur,
                   float* __restrict__ out)
{
    __shared__ int   sh_his[SEQ_LEN];  // 32 KB
    __shared__ float tbl[T_DIM];       // 4 KB

    const int tid = threadIdx.x;

    // Stage his once per block.
    {
        const int4* hg = reinterpret_cast<const int4*>(his);
        int4*       hs = reinterpret_cast<int4*>(sh_his);
        #pragma unroll
        for (int k = 0; k < VEC_ITERS; k++)
            hs[tid + k * THREADS] = hg[tid + k * THREADS];
    }

    const int row0 = blockIdx.x * ROWS_PER_BLOCK;

    for (int r = 0; r < ROWS_PER_BLOCK; r++) {
        const int i = row0 + r;
        const int t = __ldg(&cur[i]);   // uniform across block

        // Load this row's normalized table (4 KB, L2-resident) into smem.
        reinterpret_cast<float4*>(tbl)[tid] =
            reinterpret_cast<const float4*>(g_ntbl)[(size_t)t * (T_DIM / 4) + tid];
        __syncthreads();   // tbl ready (also covers sh_his on r==0)

        // Gather + write; no reductions needed (table is pre-normalized).
        float4* op = reinterpret_cast<float4*>(out + (size_t)i * SEQ_LEN);
        const int4* hs = reinterpret_cast<const int4*>(sh_his);
        #pragma unroll
        for (int k = 0; k < VEC_ITERS; k++) {
            int4 h = hs[tid + k * THREADS];
            float4 o4;
            o4.x = tbl[h.x];
            o4.y = tbl[h.y];
            o4.z = tbl[h.z];
            o4.w = tbl[h.w];
            op[tid + k * THREADS] = o4;
        }
        __syncthreads();   // all gathers done before tbl is overwritten
    }
}

extern "C" void kernel_launch(void* const* d_in, const int* in_sizes, int n_in,
                              void* d_out, int out_size)
{
    const int*   his = (const int*)d_in[0];
    const int*   cur = (const int*)d_in[1];
    const float* mat = (const float*)d_in[2];
    float*       out = (float*)d_out;
    (void)in_sizes; (void)n_in; (void)out_size;

    hist_kernel<<<1, 1024>>>(his);
    table_kernel<<<T_DIM, 256>>>(mat);
    gather_kernel<<<STATE_LEN / ROWS_PER_BLOCK, THREADS>>>(his, cur, out);
}